// round 4
// baseline (speedup 1.0000x reference)
#include <cuda_runtime.h>
#include <math_constants.h>

// Problem constants (fixed by the reference)
#define NM   32      // molecules
#define NA   40      // atoms per molecule
#define NSPEC 4
#define FEAT 384     // 4*16 + 10*32
#define RCR  5.2f
#define RCA  3.5f
#define BLK  128

__global__ __launch_bounds__(BLK, 16)
void aev_kernel(const int* __restrict__ elem,
                const float* __restrict__ coords,
                float* __restrict__ out)
{
    const int bid  = blockIdx.x;        // m*NA + i
    const int m    = bid / NA;
    const int i    = bid % NA;
    const int tid  = threadIdx.x;
    const int lane = tid & 31;

    __shared__ float sdx[NA], sdy[NA], sdz[NA], sd[NA], sfcR[NA], sfcA[NA];
    __shared__ int   selem[NA];
    __shared__ int   listR[NA], listA[NA];
    __shared__ int   scnt[2];           // cntR, cntA

    // ---- Phase 1 (warp 0 only): geometry + deterministic list build, in-warp ----
    if (tid < 32) {
        const float xi = coords[(m*NA + i)*3 + 0];
        const float yi = coords[(m*NA + i)*3 + 1];
        const float zi = coords[(m*NA + i)*3 + 2];

        // atom a0 = lane (all lanes), atom a1 = lane+32 (lanes 0-7)
        bool inR0 = false, inA0 = false, inR1 = false, inA1 = false;

        {   // a0
            const int a0 = lane;
            const float* cj = coords + (m*NA + a0)*3;
            float dx = cj[0] - xi, dy = cj[1] - yi, dz = cj[2] - zi;
            float d  = sqrtf(dx*dx + dy*dy + dz*dz + 1e-12f);
            sdx[a0] = dx; sdy[a0] = dy; sdz[a0] = dz; sd[a0] = d;
            sfcR[a0] = 0.5f * __cosf((CUDART_PI_F / RCR) * d) + 0.5f;
            sfcA[a0] = 0.5f * __cosf((CUDART_PI_F / RCA) * d) + 0.5f;
            selem[a0] = elem[m*NA + a0];
            inR0 = (a0 != i) && (d < RCR);
            inA0 = (a0 != i) && (d < RCA);
        }
        if (lane < 8) {   // a1
            const int a1 = lane + 32;
            const float* cj = coords + (m*NA + a1)*3;
            float dx = cj[0] - xi, dy = cj[1] - yi, dz = cj[2] - zi;
            float d  = sqrtf(dx*dx + dy*dy + dz*dz + 1e-12f);
            sdx[a1] = dx; sdy[a1] = dy; sdz[a1] = dz; sd[a1] = d;
            sfcR[a1] = 0.5f * __cosf((CUDART_PI_F / RCR) * d) + 0.5f;
            sfcA[a1] = 0.5f * __cosf((CUDART_PI_F / RCA) * d) + 0.5f;
            selem[a1] = elem[m*NA + a1];
            inR1 = (a1 != i) && (d < RCR);
            inA1 = (a1 != i) && (d < RCA);
        }

        const unsigned bR0 = __ballot_sync(0xFFFFFFFFu, inR0);
        const unsigned bA0 = __ballot_sync(0xFFFFFFFFu, inA0);
        const unsigned bR1 = __ballot_sync(0xFFFFFFFFu, inR1);
        const unsigned bA1 = __ballot_sync(0xFFFFFFFFu, inA1);

        const unsigned lt = (1u << lane) - 1u;
        // scatter into compact ascending lists (deterministic order)
        if (inR0) listR[__popc(bR0 & lt)] = lane;
        if (inA0) listA[__popc(bA0 & lt)] = lane;
        if (inR1) listR[__popc(bR0) + __popc(bR1 & lt)] = lane + 32;
        if (inA1) listA[__popc(bA0) + __popc(bA1 & lt)] = lane + 32;
        if (lane == 0) {
            scnt[0] = __popc(bR0) + __popc(bR1);
            scnt[1] = __popc(bA0) + __popc(bA1);
        }
    }
    __syncthreads();

    const int cntR = scnt[0];
    const int cntA = scnt[1];

    // ---- Phase 2: each thread owns 3 features (f = tid, tid+128, tid+256).
    // Feature blocks of 32 are warp-aligned -> angular pid filter is warp-uniform.
    float* o = out + bid * FEAT;
    #pragma unroll
    for (int f = tid; f < FEAT; f += BLK) {
        float acc = 0.0f;
        if (f < 64) {
            // Radial: (species s, shift fr)
            const int s  = f >> 4;
            const int fr = f & 15;
            const float shf = 0.9f + 0.26875f * (float)fr;
            for (int n = 0; n < cntR; n++) {
                int j = listR[n];
                if (selem[j] == s) {
                    float dd = sd[j] - shf;
                    acc += 0.25f * __expf(-16.0f * dd * dd) * sfcR[j];
                }
            }
        } else {
            // Angular: (species-pair p10, shf_a a, shf_z t); pairs computed inline
            const int g   = f - 64;
            const int p10 = g >> 5;
            const int rem = g & 31;
            const int a   = rem >> 3;
            const int t   = rem & 7;
            const float shfa = 0.9f + 0.65f * (float)a;
            const float z = (CUDART_PI_F / 16.0f) * (float)(2*t + 1);
            float sz, cz;
            __sincosf(z, &sz, &cz);
            for (int jj = 0; jj + 1 < cntA; jj++) {
                const int j  = listA[jj];
                const int ej = selem[j];
                const float djx = sdx[j], djy = sdy[j], djz = sdz[j];
                const float dj  = sd[j],  fj  = sfcA[j];
                for (int kk = jj + 1; kk < cntA; kk++) {
                    const int k  = listA[kk];
                    const int ek = selem[k];
                    const int lo = min(ej, ek), hi = max(ej, ek);
                    const int pid = lo*NSPEC - (lo*(lo-1))/2 + (hi - lo);
                    if (pid != p10) continue;               // warp-uniform branch
                    float dk  = sd[k];
                    float dot = djx*sdx[k] + djy*sdy[k] + djz*sdz[k];
                    float c   = 0.95f * __fdividef(dot, dj * dk);  // |c| <= 0.95
                    float sn  = sqrtf(1.0f - c*c);
                    float cth = c*cz + sn*sz;               // cos(theta - z)
                    float x   = 0.5f + 0.5f*cth;
                    float x2  = x*x;
                    float x4  = x2*x2;
                    float x8  = x4*x4;
                    float x16 = x8*x8;
                    float x32 = x16*x16;                    // x^ZETA, ZETA=32
                    float dr  = 0.5f*(dj + dk) - shfa;
                    acc += 2.0f * __expf(-8.0f * dr * dr) * x32 * fj * sfcA[k];
                }
            }
        }
        o[f] = acc;
    }
}

extern "C" void kernel_launch(void* const* d_in, const int* in_sizes, int n_in,
                              void* d_out, int out_size)
{
    const int*   elem   = (const int*)  d_in[0];   // elem_idxs (M*A) int32
    const float* coords = (const float*)d_in[1];   // coords (M*A*3) float32
    float*       out    = (float*)d_out;           // (M*A*FEAT) float32
    (void)in_sizes; (void)n_in; (void)out_size;
    aev_kernel<<<NM * NA, BLK>>>(elem, coords, out);
}

// round 5
// speedup vs baseline: 2.1185x; 2.1185x over previous
#include <cuda_runtime.h>
#include <math_constants.h>

// Problem constants (fixed by the reference)
#define NM   32      // molecules
#define NA   40      // atoms per molecule
#define NSPEC 4
#define FEAT 384     // 4*16 + 10*32
#define RCR  5.2f
#define RCA  3.5f
#define MAXP (NA*(NA-1)/2)   // 780 worst-case angular pairs
#define BLK  128

__global__ __launch_bounds__(BLK, 8)
void aev_kernel(const int* __restrict__ elem,
                const float* __restrict__ coords,
                float* __restrict__ out)
{
    const int bid  = blockIdx.x;        // m*NA + i
    const int m    = bid / NA;
    const int i    = bid % NA;
    const int tid  = threadIdx.x;
    const int lane = tid & 31;

    // Compacted angular-candidate geometry (index = compact position, ascending)
    __shared__ float adx[NA], ady[NA], adz[NA], ad[NA], afc[NA];
    __shared__ int   aelem[NA];
    // Compacted radial neighbors
    __shared__ float2 rdat[NA];         // {d, fcR}
    __shared__ int    relem[NA];
    __shared__ int    scnt[2];          // cntR, cntA
    // Precomputed pair records
    __shared__ float4 pdat[MAXP];       // {ca, sa, rmean, fc_j*fc_k}
    __shared__ int    ppid[MAXP];

    // ---- Phase 1 (warp 0 only): geometry + ballots + COMPACTED scatter ----
    if (tid < 32) {
        const float xi = coords[(m*NA + i)*3 + 0];
        const float yi = coords[(m*NA + i)*3 + 1];
        const float zi = coords[(m*NA + i)*3 + 2];

        // atom a0 = lane (all lanes), atom a1 = lane+32 (lanes 0-7)
        bool inR0 = false, inA0 = false, inR1 = false, inA1 = false;
        float dx0=0, dy0=0, dz0=0, d0=0, fA0=0, fR0=0;
        float dx1=0, dy1=0, dz1=0, d1=0, fA1=0, fR1=0;
        int   e0=0, e1v=0;

        {   // a0
            const float* cj = coords + (m*NA + lane)*3;
            dx0 = cj[0] - xi; dy0 = cj[1] - yi; dz0 = cj[2] - zi;
            d0  = sqrtf(dx0*dx0 + dy0*dy0 + dz0*dz0 + 1e-12f);
            fR0 = 0.5f * __cosf((CUDART_PI_F / RCR) * d0) + 0.5f;
            fA0 = 0.5f * __cosf((CUDART_PI_F / RCA) * d0) + 0.5f;
            e0  = elem[m*NA + lane];
            inR0 = (lane != i) && (d0 < RCR);
            inA0 = (lane != i) && (d0 < RCA);
        }
        if (lane < 8) {   // a1
            const int a1 = lane + 32;
            const float* cj = coords + (m*NA + a1)*3;
            dx1 = cj[0] - xi; dy1 = cj[1] - yi; dz1 = cj[2] - zi;
            d1  = sqrtf(dx1*dx1 + dy1*dy1 + dz1*dz1 + 1e-12f);
            fR1 = 0.5f * __cosf((CUDART_PI_F / RCR) * d1) + 0.5f;
            fA1 = 0.5f * __cosf((CUDART_PI_F / RCA) * d1) + 0.5f;
            e1v = elem[m*NA + a1];
            inR1 = (a1 != i) && (d1 < RCR);
            inA1 = (a1 != i) && (d1 < RCA);
        }

        const unsigned bR0 = __ballot_sync(0xFFFFFFFFu, inR0);
        const unsigned bA0 = __ballot_sync(0xFFFFFFFFu, inA0);
        const unsigned bR1 = __ballot_sync(0xFFFFFFFFu, inR1);
        const unsigned bA1 = __ballot_sync(0xFFFFFFFFu, inA1);
        const unsigned lt  = (1u << lane) - 1u;

        // Scatter COMPACTED data directly (ascending deterministic order)
        if (inA0) {
            int p = __popc(bA0 & lt);
            adx[p]=dx0; ady[p]=dy0; adz[p]=dz0; ad[p]=d0; afc[p]=fA0; aelem[p]=e0;
        }
        if (inA1) {
            int p = __popc(bA0) + __popc(bA1 & lt);
            adx[p]=dx1; ady[p]=dy1; adz[p]=dz1; ad[p]=d1; afc[p]=fA1; aelem[p]=e1v;
        }
        if (inR0) {
            int p = __popc(bR0 & lt);
            rdat[p] = make_float2(d0, fR0); relem[p] = e0;
        }
        if (inR1) {
            int p = __popc(bR0) + __popc(bR1 & lt);
            rdat[p] = make_float2(d1, fR1); relem[p] = e1v;
        }
        if (lane == 0) {
            scnt[0] = __popc(bR0) + __popc(bR1);
            scnt[1] = __popc(bA0) + __popc(bA1);
        }
    }
    __syncthreads();

    const int cntR = scnt[0];
    const int cntA = scnt[1];
    const int np   = cntA * (cntA - 1) / 2;

    // ---- Phase 2 (all threads): pair invariants from compacted arrays ----
    for (int p = tid; p < np; p += BLK) {
        int jj = 0, rem = p, row = cntA - 1;
        while (rem >= row) { rem -= row; row--; jj++; }
        int kk = jj + 1 + rem;
        float dot = adx[jj]*adx[kk] + ady[jj]*ady[kk] + adz[jj]*adz[kk];
        float dj = ad[jj], dk = ad[kk];
        float c  = 0.95f * __fdividef(dot, dj * dk);   // |c| <= 0.95
        float sn = sqrtf(1.0f - c*c);                  // sin(acos(c)) >= 0
        pdat[p] = make_float4(c, sn, 0.5f*(dj + dk), afc[jj]*afc[kk]);
        int ej = aelem[jj], ek = aelem[kk];
        int lo = min(ej, ek), hi = max(ej, ek);
        ppid[p] = lo*NSPEC - (lo*(lo-1))/2 + (hi - lo);
    }
    __syncthreads();

    // ---- Phase 3: each thread owns 3 features (f = tid, tid+128, tid+256).
    // Feature blocks of 32 are warp-aligned -> angular pid filter is warp-uniform,
    // and all smem reads below are warp-uniform broadcasts (conflict-free).
    float* o = out + bid * FEAT;
    #pragma unroll
    for (int f = tid; f < FEAT; f += BLK) {
        float acc = 0.0f;
        if (f < 64) {
            // Radial: (species s, shift fr)
            const int s  = f >> 4;
            const int fr = f & 15;
            const float shf = 0.9f + 0.26875f * (float)fr;
            #pragma unroll 4
            for (int n = 0; n < cntR; n++) {
                float2 rd = rdat[n];
                int    re = relem[n];
                float dd = rd.x - shf;
                float t  = 0.25f * __expf(-16.0f * dd * dd) * rd.y;
                acc += (re == s) ? t : 0.0f;
            }
        } else {
            // Angular: (species-pair p10, shf_a a, shf_z t)
            const int g   = f - 64;
            const int p10 = g >> 5;
            const int rem = g & 31;
            const int a   = rem >> 3;
            const int t   = rem & 7;
            const float shfa = 0.9f + 0.65f * (float)a;
            const float z = (CUDART_PI_F / 16.0f) * (float)(2*t + 1);
            float sz, cz;
            __sincosf(z, &sz, &cz);
            #pragma unroll 4
            for (int p = 0; p < np; p++) {
                int    pid = ppid[p];
                float4 pd  = pdat[p];                 // broadcast LDS.128
                if (pid != p10) continue;             // warp-uniform
                float cth = pd.x*cz + pd.y*sz;        // cos(theta - z)
                float x   = 0.5f + 0.5f*cth;
                float x2  = x*x;
                float x4  = x2*x2;
                float x8  = x4*x4;
                float x16 = x8*x8;
                float x32 = x16*x16;                  // x^ZETA, ZETA=32
                float dr  = pd.z - shfa;
                acc += 2.0f * __expf(-8.0f * dr * dr) * x32 * pd.w;
            }
        }
        o[f] = acc;
    }
}

extern "C" void kernel_launch(void* const* d_in, const int* in_sizes, int n_in,
                              void* d_out, int out_size)
{
    const int*   elem   = (const int*)  d_in[0];   // elem_idxs (M*A) int32
    const float* coords = (const float*)d_in[1];   // coords (M*A*3) float32
    float*       out    = (float*)d_out;           // (M*A*FEAT) float32
    (void)in_sizes; (void)n_in; (void)out_size;
    aev_kernel<<<NM * NA, BLK>>>(elem, coords, out);
}

// round 6
// speedup vs baseline: 2.2623x; 1.0679x over previous
#include <cuda_runtime.h>
#include <math_constants.h>

// Problem constants (fixed by the reference)
#define NM   32      // molecules
#define NA   40      // atoms per molecule
#define NSPEC 4
#define FEAT 384     // 4*16 + 10*32
#define RCR  5.2f
#define RCA  3.5f
#define BLK  128
#define CHUNK 128    // pair records staged per iteration (covers realistic np in 1 pass)

__global__ __launch_bounds__(BLK)
void aev_kernel(const int* __restrict__ elem,
                const float* __restrict__ coords,
                float* __restrict__ out)
{
    const int bid  = blockIdx.x;        // m*NA + i
    const int m    = bid / NA;
    const int i    = bid % NA;
    const int tid  = threadIdx.x;
    const int lane = tid & 31;

    // Compacted angular-candidate geometry (index = compact position, ascending)
    __shared__ float adx[NA], ady[NA], adz[NA], ad[NA], afc[NA];
    __shared__ int   aelem[NA];
    // Compacted radial neighbors
    __shared__ float2 rdat[NA];         // {d, fcR}
    __shared__ int    relem[NA];
    __shared__ int    scnt[2];          // cntR, cntA
    // Pair records, staged in chunks (small smem -> full residency, 1 wave)
    __shared__ float4 pdat[CHUNK];      // {ca, sa, rmean, fc_j*fc_k}
    __shared__ int    ppid[CHUNK];

    // ---- Phase 1 (warp 0 only): geometry + ballots + compacted scatter ----
    if (tid < 32) {
        const float xi = coords[(m*NA + i)*3 + 0];
        const float yi = coords[(m*NA + i)*3 + 1];
        const float zi = coords[(m*NA + i)*3 + 2];

        bool inR0 = false, inA0 = false, inR1 = false, inA1 = false;
        float dx0=0, dy0=0, dz0=0, d0=0, fA0=0, fR0=0;
        float dx1=0, dy1=0, dz1=0, d1=0, fA1=0, fR1=0;
        int   e0=0, e1v=0;

        {   // atom a0 = lane
            const float* cj = coords + (m*NA + lane)*3;
            dx0 = cj[0] - xi; dy0 = cj[1] - yi; dz0 = cj[2] - zi;
            d0  = sqrtf(dx0*dx0 + dy0*dy0 + dz0*dz0 + 1e-12f);
            fR0 = 0.5f * __cosf((CUDART_PI_F / RCR) * d0) + 0.5f;
            fA0 = 0.5f * __cosf((CUDART_PI_F / RCA) * d0) + 0.5f;
            e0  = elem[m*NA + lane];
            inR0 = (lane != i) && (d0 < RCR);
            inA0 = (lane != i) && (d0 < RCA);
        }
        if (lane < 8) {   // atom a1 = lane+32
            const int a1 = lane + 32;
            const float* cj = coords + (m*NA + a1)*3;
            dx1 = cj[0] - xi; dy1 = cj[1] - yi; dz1 = cj[2] - zi;
            d1  = sqrtf(dx1*dx1 + dy1*dy1 + dz1*dz1 + 1e-12f);
            fR1 = 0.5f * __cosf((CUDART_PI_F / RCR) * d1) + 0.5f;
            fA1 = 0.5f * __cosf((CUDART_PI_F / RCA) * d1) + 0.5f;
            e1v = elem[m*NA + a1];
            inR1 = (a1 != i) && (d1 < RCR);
            inA1 = (a1 != i) && (d1 < RCA);
        }

        const unsigned bR0 = __ballot_sync(0xFFFFFFFFu, inR0);
        const unsigned bA0 = __ballot_sync(0xFFFFFFFFu, inA0);
        const unsigned bR1 = __ballot_sync(0xFFFFFFFFu, inR1);
        const unsigned bA1 = __ballot_sync(0xFFFFFFFFu, inA1);
        const unsigned lt  = (1u << lane) - 1u;

        if (inA0) {
            int p = __popc(bA0 & lt);
            adx[p]=dx0; ady[p]=dy0; adz[p]=dz0; ad[p]=d0; afc[p]=fA0; aelem[p]=e0;
        }
        if (inA1) {
            int p = __popc(bA0) + __popc(bA1 & lt);
            adx[p]=dx1; ady[p]=dy1; adz[p]=dz1; ad[p]=d1; afc[p]=fA1; aelem[p]=e1v;
        }
        if (inR0) {
            int p = __popc(bR0 & lt);
            rdat[p] = make_float2(d0, fR0); relem[p] = e0;
        }
        if (inR1) {
            int p = __popc(bR0) + __popc(bR1 & lt);
            rdat[p] = make_float2(d1, fR1); relem[p] = e1v;
        }
        if (lane == 0) {
            scnt[0] = __popc(bR0) + __popc(bR1);
            scnt[1] = __popc(bA0) + __popc(bA1);
        }
    }
    __syncthreads();

    const int cntR = scnt[0];
    const int cntA = scnt[1];
    const int np   = cntA * (cntA - 1) / 2;

    // ---- Slot setup: thread owns features f = tid, tid+128, tid+256 ----
    // Slot 0 for tid<64 is RADIAL (p10 = -1, never matches a pair pid).
    int   p10s[3];
    float shfas[3], szs[3], czs[3], acc[3];
    #pragma unroll
    for (int s = 0; s < 3; s++) {
        const int f = tid + 128*s;
        acc[s] = 0.0f;
        if (f < 64) {
            p10s[s] = -1; shfas[s] = 0.0f; szs[s] = 0.0f; czs[s] = 0.0f;
        } else {
            const int g = f - 64;
            p10s[s] = g >> 5;
            const int a = (g >> 3) & 3;
            const int t = g & 7;
            shfas[s] = 0.9f + 0.65f * (float)a;
            const float z = (CUDART_PI_F / 16.0f) * (float)(2*t + 1);
            __sincosf(z, &szs[s], &czs[s]);
        }
    }

    // ---- Radial features (threads 0..63, slot 0), independent of pairs ----
    if (tid < 64) {
        const int s  = tid >> 4;
        const int fr = tid & 15;
        const float shf = 0.9f + 0.26875f * (float)fr;
        float r = 0.0f;
        #pragma unroll 4
        for (int n = 0; n < cntR; n++) {
            float2 rd = rdat[n];
            int    re = relem[n];
            float dd = rd.x - shf;
            float t  = 0.25f * __expf(-16.0f * dd * dd) * rd.y;
            r += (re == s) ? t : 0.0f;
        }
        acc[0] = r;
    }

    // ---- Pair chunks: build CHUNK records, then one fused scan for all 3 slots ----
    for (int base = 0; base < np; base += CHUNK) {
        const int n = min(CHUNK, np - base);
        for (int p = tid; p < n; p += BLK) {
            const int q = base + p;
            int jj = 0, rem = q, row = cntA - 1;
            while (rem >= row) { rem -= row; row--; jj++; }
            int kk = jj + 1 + rem;
            float dot = adx[jj]*adx[kk] + ady[jj]*ady[kk] + adz[jj]*adz[kk];
            float dj = ad[jj], dk = ad[kk];
            float c  = 0.95f * __fdividef(dot, dj * dk);   // |c| <= 0.95
            float sn = sqrtf(1.0f - c*c);                  // sin(acos(c)) >= 0
            pdat[p] = make_float4(c, sn, 0.5f*(dj + dk), afc[jj]*afc[kk]);
            int ej = aelem[jj], ek = aelem[kk];
            int lo = min(ej, ek), hi = max(ej, ek);
            ppid[p] = lo*NSPEC - (lo*(lo-1))/2 + (hi - lo);
        }
        __syncthreads();

        #pragma unroll 2
        for (int p = 0; p < n; p++) {
            const int    pid = ppid[p];    // warp-uniform broadcast
            const float4 pd  = pdat[p];    // broadcast LDS.128
            #pragma unroll
            for (int s = 0; s < 3; s++) {
                if (pid == p10s[s]) {      // warp-uniform per slot
                    float cth = pd.x*czs[s] + pd.y*szs[s];   // cos(theta - z)
                    float x   = 0.5f + 0.5f*cth;
                    float x2  = x*x;
                    float x4  = x2*x2;
                    float x8  = x4*x4;
                    float x16 = x8*x8;
                    float x32 = x16*x16;                      // x^32
                    float dr  = pd.z - shfas[s];
                    acc[s] += 2.0f * __expf(-8.0f * dr * dr) * x32 * pd.w;
                }
            }
        }
        __syncthreads();
    }

    // ---- Store: coalesced 384-float write ----
    float* o = out + bid * FEAT;
    o[tid]       = acc[0];
    o[tid + 128] = acc[1];
    o[tid + 256] = acc[2];
}

extern "C" void kernel_launch(void* const* d_in, const int* in_sizes, int n_in,
                              void* d_out, int out_size)
{
    const int*   elem   = (const int*)  d_in[0];   // elem_idxs (M*A) int32
    const float* coords = (const float*)d_in[1];   // coords (M*A*3) float32
    float*       out    = (float*)d_out;           // (M*A*FEAT) float32
    (void)in_sizes; (void)n_in; (void)out_size;
    aev_kernel<<<NM * NA, BLK>>>(elem, coords, out);
}

// round 7
// speedup vs baseline: 2.6085x; 1.1530x over previous
#include <cuda_runtime.h>
#include <math_constants.h>

// Problem constants (fixed by the reference)
#define NM   32      // molecules
#define NA   40      // atoms per molecule
#define NSPEC 4
#define FEAT 384     // 4*16 + 10*32
#define RCR  5.2f
#define RCA  3.5f
#define BLK  128
#define CHUNK 128    // pair records staged per iteration

__global__ __launch_bounds__(BLK)
void aev_kernel(const int* __restrict__ elem,
                const float* __restrict__ coords,
                float* __restrict__ out)
{
    const int bid  = blockIdx.x;        // m*NA + i
    const int m    = bid / NA;
    const int i    = bid % NA;
    const int tid  = threadIdx.x;
    const int lane = tid & 31;
    const int w    = tid >> 5;

    // Compacted angular-candidate geometry (ascending deterministic order)
    __shared__ float adx[NA], ady[NA], adz[NA], ad[NA], afc[NA];
    __shared__ int   aelem[NA];
    // Compacted radial neighbors
    __shared__ float2 rdat[NA];         // {d, fcR}
    __shared__ int    relem[NA];
    __shared__ int    scnt[2];          // cntR, cntA
    // Pair records, staged per chunk
    __shared__ float4 pdat[CHUNK];      // {ca, sa, rmean, fc_j*fc_k}
    __shared__ int    ppid[CHUNK];
    // Warp-3 angular partials (padded stride 11 -> conflict-free)
    __shared__ float  angp[32][11];

    // ---- Phase 1 (warp 0 only): geometry + ballots + compacted scatter ----
    if (w == 0) {
        const float xi = coords[(m*NA + i)*3 + 0];
        const float yi = coords[(m*NA + i)*3 + 1];
        const float zi = coords[(m*NA + i)*3 + 2];

        bool inR0 = false, inA0 = false, inR1 = false, inA1 = false;
        float dx0=0, dy0=0, dz0=0, d0=0, fA0=0, fR0=0;
        float dx1=0, dy1=0, dz1=0, d1=0, fA1=0, fR1=0;
        int   e0=0, e1v=0;

        {   // atom a0 = lane
            const float* cj = coords + (m*NA + lane)*3;
            dx0 = cj[0] - xi; dy0 = cj[1] - yi; dz0 = cj[2] - zi;
            d0  = sqrtf(dx0*dx0 + dy0*dy0 + dz0*dz0 + 1e-12f);
            fR0 = 0.5f * __cosf((CUDART_PI_F / RCR) * d0) + 0.5f;
            fA0 = 0.5f * __cosf((CUDART_PI_F / RCA) * d0) + 0.5f;
            e0  = elem[m*NA + lane];
            inR0 = (lane != i) && (d0 < RCR);
            inA0 = (lane != i) && (d0 < RCA);
        }
        if (lane < 8) {   // atom a1 = lane+32
            const int a1 = lane + 32;
            const float* cj = coords + (m*NA + a1)*3;
            dx1 = cj[0] - xi; dy1 = cj[1] - yi; dz1 = cj[2] - zi;
            d1  = sqrtf(dx1*dx1 + dy1*dy1 + dz1*dz1 + 1e-12f);
            fR1 = 0.5f * __cosf((CUDART_PI_F / RCR) * d1) + 0.5f;
            fA1 = 0.5f * __cosf((CUDART_PI_F / RCA) * d1) + 0.5f;
            e1v = elem[m*NA + a1];
            inR1 = (a1 != i) && (d1 < RCR);
            inA1 = (a1 != i) && (d1 < RCA);
        }

        const unsigned bR0 = __ballot_sync(0xFFFFFFFFu, inR0);
        const unsigned bA0 = __ballot_sync(0xFFFFFFFFu, inA0);
        const unsigned bR1 = __ballot_sync(0xFFFFFFFFu, inR1);
        const unsigned bA1 = __ballot_sync(0xFFFFFFFFu, inA1);
        const unsigned lt  = (1u << lane) - 1u;

        if (inA0) {
            int p = __popc(bA0 & lt);
            adx[p]=dx0; ady[p]=dy0; adz[p]=dz0; ad[p]=d0; afc[p]=fA0; aelem[p]=e0;
        }
        if (inA1) {
            int p = __popc(bA0) + __popc(bA1 & lt);
            adx[p]=dx1; ady[p]=dy1; adz[p]=dz1; ad[p]=d1; afc[p]=fA1; aelem[p]=e1v;
        }
        if (inR0) {
            int p = __popc(bR0 & lt);
            rdat[p] = make_float2(d0, fR0); relem[p] = e0;
        }
        if (inR1) {
            int p = __popc(bR0) + __popc(bR1 & lt);
            rdat[p] = make_float2(d1, fR1); relem[p] = e1v;
        }
        if (lane == 0) {
            scnt[0] = __popc(bR0) + __popc(bR1);
            scnt[1] = __popc(bA0) + __popc(bA1);
        }
    }
    __syncthreads();

    const int cntR = scnt[0];
    const int cntA = scnt[1];
    const int np   = cntA * (cntA - 1) / 2;

    float* o = out + bid * FEAT;

    // ---- Radial features (threads 0..63), independent of pairs ----
    if (tid < 64) {
        const int s  = tid >> 4;
        const int fr = tid & 15;
        const float shf = 0.9f + 0.26875f * (float)fr;
        float r = 0.0f;
        #pragma unroll 4
        for (int n = 0; n < cntR; n++) {
            float2 rd = rdat[n];
            int    re = relem[n];
            float dd = rd.x - shf;
            float t  = 0.25f * __expf(-16.0f * dd * dd) * rd.y;
            r += (re == s) ? t : 0.0f;
        }
        o[tid] = r;
    }

    // ---- Angular setup (warps 2,3): lane owns one (a,t), all 10 pids ----
    float aacc[10];
    #pragma unroll
    for (int q = 0; q < 10; q++) aacc[q] = 0.0f;
    float sz = 0.0f, cz = 0.0f, shfa = 0.0f;
    if (w >= 2) {
        const int a = lane >> 3;
        const int t = lane & 7;
        shfa = 0.9f + 0.65f * (float)a;
        const float z = (CUDART_PI_F / 16.0f) * (float)(2*t + 1);
        __sincosf(z, &sz, &cz);
    }

    // ---- Pair chunks: all threads build; warps 2/3 scan even/odd pairs ----
    for (int base = 0; base < np; base += CHUNK) {
        const int n = min(CHUNK, np - base);
        for (int p = tid; p < n; p += BLK) {
            const int q = base + p;
            int jj = 0, rem = q, row = cntA - 1;
            while (rem >= row) { rem -= row; row--; jj++; }
            int kk = jj + 1 + rem;
            float dot = adx[jj]*adx[kk] + ady[jj]*ady[kk] + adz[jj]*adz[kk];
            float dj = ad[jj], dk = ad[kk];
            float c  = 0.95f * __fdividef(dot, dj * dk);   // |c| <= 0.95
            float sn = sqrtf(1.0f - c*c);                  // sin(acos(c)) >= 0
            pdat[p] = make_float4(c, sn, 0.5f*(dj + dk), afc[jj]*afc[kk]);
            int ej = aelem[jj], ek = aelem[kk];
            int lo = min(ej, ek), hi = max(ej, ek);
            ppid[p] = lo*NSPEC - (lo*(lo-1))/2 + (hi - lo);
        }
        __syncthreads();

        if (w >= 2) {
            // warp 2: even pairs; warp 3: odd pairs. Branchless body.
            for (int p = (w - 2); p < n; p += 2) {
                const int    pid = ppid[p];    // warp-uniform broadcast
                const float4 pd  = pdat[p];    // broadcast LDS.128
                float cth = pd.x*cz + pd.y*sz; // cos(theta - z)
                float x   = 0.5f + 0.5f*cth;
                float x2  = x*x;
                float x4  = x2*x2;
                float x8  = x4*x4;
                float x16 = x8*x8;
                float x32 = x16*x16;           // x^ZETA, ZETA=32
                float dr  = pd.z - shfa;
                float term = 2.0f * __expf(-8.0f * dr * dr) * x32 * pd.w;
                #pragma unroll
                for (int q = 0; q < 10; q++)
                    aacc[q] += (pid == q) ? term : 0.0f;   // select-add, no branch
            }
        }
        __syncthreads();
    }

    // ---- Combine warp 2 + warp 3 partials and store (coalesced per pid row) ----
    if (w == 3) {
        #pragma unroll
        for (int q = 0; q < 10; q++) angp[lane][q] = aacc[q];
    }
    __syncthreads();
    if (w == 2) {
        #pragma unroll
        for (int q = 0; q < 10; q++)
            o[64 + q*32 + lane] = aacc[q] + angp[lane][q];
    }
}

extern "C" void kernel_launch(void* const* d_in, const int* in_sizes, int n_in,
                              void* d_out, int out_size)
{
    const int*   elem   = (const int*)  d_in[0];   // elem_idxs (M*A) int32
    const float* coords = (const float*)d_in[1];   // coords (M*A*3) float32
    float*       out    = (float*)d_out;           // (M*A*FEAT) float32
    (void)in_sizes; (void)n_in; (void)out_size;
    aev_kernel<<<NM * NA, BLK>>>(elem, coords, out);
}